// round 8
// baseline (speedup 1.0000x reference)
#include <cuda_runtime.h>
#include <cstdint>

#define DD 128   // obs dim
#define FF 80    // features
#define AA 18    // actions
#define TM 128   // samples per tile
#define NT 256   // threads (8 warps, one 16-row m-tile each)
#define XS 136   // smem row stride (floats): conflict-free for LDS.64 frags

#define OFF_X 1024                        // X/H tile: [128][XS] floats
#define OFF_W (OFF_X + TM * XS * 4)       // W tile:   [80][XS] floats
#define SMEM_BYTES (OFF_W + FF * XS * 4)  // 114,176 B -> 2 CTAs/SM

// fp32 -> tf32 (round to nearest)
__device__ __forceinline__ uint32_t f2tf(float f) {
    uint32_t u;
    asm("cvt.rna.tf32.f32 %0, %1;" : "=r"(u) : "f"(f));
    return u;
}

__device__ __forceinline__ void mma8(float c[4], const uint32_t a[4],
                                     uint32_t b0, uint32_t b1) {
    asm volatile(
        "mma.sync.aligned.m16n8k8.row.col.f32.tf32.tf32.f32 "
        "{%0,%1,%2,%3}, {%4,%5,%6,%7}, {%8,%9}, {%0,%1,%2,%3};"
        : "+f"(c[0]), "+f"(c[1]), "+f"(c[2]), "+f"(c[3])
        : "r"(a[0]), "r"(a[1]), "r"(a[2]), "r"(a[3]), "r"(b0), "r"(b1));
}

// Store one 8-col group (logical cols g8*8..+7) permuted for v2 fragment loads:
// physical order [c0,c4,c1,c5 | c2,c6,c3,c7]  (phys(cc) = (cc&3)*2 + (cc>>2))
__device__ __forceinline__ void store_group(uint32_t* s, int row, int g8,
                                            float4 a, float4 b) {
    uint32_t* p = s + row * XS + g8 * 8;
    *(uint4*)p = make_uint4(f2tf(a.x), f2tf(b.x), f2tf(a.y), f2tf(b.y));
    *(uint4*)(p + 4) = make_uint4(f2tf(a.z), f2tf(b.z), f2tf(a.w), f2tf(b.w));
}

// Warp-level GEMM: acc[n][4] += X[R0..R0+16) x W[n*8..+8)^T, K = KS*8.
// All operand loads are conflict-free LDS.64.
template <int KS, int NTL>
__device__ __forceinline__ void mma_layer(const uint32_t* __restrict__ sx,
                                          const uint32_t* __restrict__ sw,
                                          float acc[NTL][4], int R0, int l) {
    const uint32_t* pa = sx + (R0 + (l >> 2)) * XS + 2 * (l & 3);
    const uint32_t* pw = sw + (l >> 2) * XS + 2 * (l & 3);
#pragma unroll
    for (int k = 0; k < KS; ++k) {
        uint2 a0 = *(const uint2*)(pa + k * 8);
        uint2 a1 = *(const uint2*)(pa + 8 * XS + k * 8);
        uint32_t A[4] = {a0.x, a1.x, a0.y, a1.y};
#pragma unroll
        for (int n = 0; n < NTL; ++n) {
            uint2 b = *(const uint2*)(pw + n * 8 * XS + k * 8);
            mma8(acc[n], A, b.x, b.y);
        }
    }
}

__global__ void __launch_bounds__(NT, 2)
gym_mma(const float* __restrict__ state, const int* __restrict__ idx,
        const float* __restrict__ W1, const float* __restrict__ b1,
        const float* __restrict__ W2, const float* __restrict__ b2,
        const float* __restrict__ W3, const float* __restrict__ b3,
        const float* __restrict__ W4, const float* __restrict__ b4,
        float* __restrict__ out) {
    extern __shared__ char smem[];
    int* s_idx = (int*)smem;               // 512 B
    float* s_bias = (float*)(smem + 512);  // 512 B
    uint32_t* sx = (uint32_t*)(smem + OFF_X);
    uint32_t* sw = (uint32_t*)(smem + OFF_W);

    const int tid = threadIdx.x;
    const int l = tid & 31;
    const int R0 = (tid >> 5) * 16;  // warp's 16-row m-tile
    const int m0 = blockIdx.x * TM;
    const int m = l & 3, qr = l >> 2;
    const int p0 = (m & 1) * 4 + (m >> 1);  // phys col of logical 2m
    const int p1 = p0 + 2;                  // phys col of logical 2m+1

    // ---- idx + X tile (tf32, permuted groups) ----
    if (tid < TM) s_idx[tid] = idx[m0 + tid];
    {
        const float4* gx = (const float4*)(state + (size_t)m0 * DD);
#pragma unroll
        for (int b = 0; b < TM * 16; b += NT) {   // 2048 groups
            int i = b + tid;
            int r = i >> 4, g8 = i & 15;
            store_group(sx, r, g8, gx[r * 32 + g8 * 2], gx[r * 32 + g8 * 2 + 1]);
        }
    }
    __syncthreads();

    const int g_lo = s_idx[0];
    const int g_hi = s_idx[TM - 1];        // sorted idx
    const int rg0 = s_idx[R0 + qr];        // game of fragment row r
    const int rg1 = s_idx[R0 + 8 + qr];    // game of fragment row r+8
    const int bc = 2 * m;                  // logical col within n-group: bias idx

    // ================= Layer 1 (routed, K=128, N=80) =================
    for (int g = g_lo; g <= g_hi; ++g) {
        __syncthreads();  // prior mma done with sw
        {
            const float4* gw = (const float4*)(W1 + (size_t)g * FF * DD);
#pragma unroll
            for (int b = 0; b < FF * 16; b += NT) {  // 1280 groups
                int i = b + tid;
                int r = i >> 4, g8 = i & 15;
                store_group(sw, r, g8, gw[r * 32 + g8 * 2], gw[r * 32 + g8 * 2 + 1]);
            }
            if (tid < FF) s_bias[tid] = b1[g * FF + tid];
        }
        __syncthreads();

        float acc[10][4];
#pragma unroll
        for (int n = 0; n < 10; ++n) {
            float bv0 = s_bias[n * 8 + bc], bv1 = s_bias[n * 8 + bc + 1];
            acc[n][0] = bv0; acc[n][1] = bv1; acc[n][2] = bv0; acc[n][3] = bv1;
        }
        mma_layer<16, 10>(sx, sw, acc, R0, l);

        // write H (relu) back into own m-tile rows under game predicate;
        // other warps never read these rows, so no cross-warp hazard.
        const bool t0 = (rg0 == g), t1 = (rg1 == g);
        uint32_t* row0 = sx + (R0 + qr) * XS;
        uint32_t* row1 = row0 + 8 * XS;
#pragma unroll
        for (int n = 0; n < 10; ++n) {
            if (t0) {
                row0[n * 8 + p0] = f2tf(fmaxf(acc[n][0], 0.f));
                row0[n * 8 + p1] = f2tf(fmaxf(acc[n][1], 0.f));
            }
            if (t1) {
                row1[n * 8 + p0] = f2tf(fmaxf(acc[n][2], 0.f));
                row1[n * 8 + p1] = f2tf(fmaxf(acc[n][3], 0.f));
            }
        }
    }

    // ================= Layers 2 & 3 (shared, K=80, N=80) =================
#pragma unroll 1
    for (int layer = 0; layer < 2; ++layer) {
        const float* Wl = layer ? W3 : W2;
        const float* bl = layer ? b3 : b2;
        __syncthreads();  // all warps done with sw (and own sx rows final)
        {
            const float4* gw = (const float4*)Wl;
            for (int i = tid; i < FF * 10; i += NT) {  // 800 groups
                int r = i / 10, g8 = i - r * 10;
                store_group(sw, r, g8, gw[r * 20 + g8 * 2], gw[r * 20 + g8 * 2 + 1]);
            }
            if (tid < FF) s_bias[tid] = bl[tid];
        }
        __syncthreads();

        float acc[10][4];
#pragma unroll
        for (int n = 0; n < 10; ++n) {
            float bv0 = s_bias[n * 8 + bc], bv1 = s_bias[n * 8 + bc + 1];
            acc[n][0] = bv0; acc[n][1] = bv1; acc[n][2] = bv0; acc[n][3] = bv1;
        }
        mma_layer<10, 10>(sx, sw, acc, R0, l);

        uint32_t* row0 = sx + (R0 + qr) * XS;
        uint32_t* row1 = row0 + 8 * XS;
#pragma unroll
        for (int n = 0; n < 10; ++n) {
            row0[n * 8 + p0] = f2tf(fmaxf(acc[n][0], 0.f));
            row0[n * 8 + p1] = f2tf(fmaxf(acc[n][1], 0.f));
            row1[n * 8 + p0] = f2tf(fmaxf(acc[n][2], 0.f));
            row1[n * 8 + p1] = f2tf(fmaxf(acc[n][3], 0.f));
        }
    }

    // ================= Layer 4 (routed head, N=18 pad 24) =================
    __syncthreads();  // sw free; zero pad rows 18..23 once
    for (int i = tid; i < 6 * 10; i += NT) {
        int r = 18 + i / 10, g8 = i % 10;
        *(uint4*)&sw[r * XS + g8 * 8] = make_uint4(0u, 0u, 0u, 0u);
        *(uint4*)&sw[r * XS + g8 * 8 + 4] = make_uint4(0u, 0u, 0u, 0u);
    }

    float facc4[3][4];
    for (int g = g_lo; g <= g_hi; ++g) {
        __syncthreads();  // pad visible / prior mma done with sw
        {
            const float4* gw = (const float4*)(W4 + (size_t)g * AA * FF);
            for (int i = tid; i < AA * 10; i += NT) {  // 180 groups
                int r = i / 10, g8 = i - r * 10;
                store_group(sw, r, g8, gw[r * 20 + g8 * 2], gw[r * 20 + g8 * 2 + 1]);
            }
            if (tid < 32) s_bias[tid] = (tid < AA) ? b4[g * AA + tid] : 0.f;
        }
        __syncthreads();

        float acc[3][4];
#pragma unroll
        for (int n = 0; n < 3; ++n) {
            float bv0 = s_bias[n * 8 + bc], bv1 = s_bias[n * 8 + bc + 1];
            acc[n][0] = bv0; acc[n][1] = bv1; acc[n][2] = bv0; acc[n][3] = bv1;
        }
        mma_layer<10, 3>(sx, sw, acc, R0, l);

        const bool t0 = (rg0 == g), t1 = (rg1 == g);
#pragma unroll
        for (int n = 0; n < 3; ++n) {
            if (t0) { facc4[n][0] = acc[n][0]; facc4[n][1] = acc[n][1]; }
            if (t1) { facc4[n][2] = acc[n][2]; facc4[n][3] = acc[n][3]; }
        }
    }

    // stage q through smem (sw region free after final sync) for coalesced stores
    __syncthreads();
    float* s_out = (float*)sw;  // [128][18]
    {
        int r = R0 + qr;
#pragma unroll
        for (int n = 0; n < 3; ++n) {
            int c = n * 8 + bc;
            if (c < AA) {
                s_out[r * AA + c] = facc4[n][0];
                s_out[(r + 8) * AA + c] = facc4[n][2];
                if (c + 1 < AA) {
                    s_out[r * AA + c + 1] = facc4[n][1];
                    s_out[(r + 8) * AA + c + 1] = facc4[n][3];
                }
            }
        }
    }
    __syncthreads();
    {
        float4* go = (float4*)(out + (size_t)m0 * AA);
        const float4* so = (const float4*)s_out;
        for (int i = tid; i < TM * AA / 4; i += NT) go[i] = so[i];
    }
}

extern "C" void kernel_launch(void* const* d_in, const int* in_sizes, int n_in,
                              void* d_out, int out_size) {
    const float* state = (const float*)d_in[0];
    const int* idx     = (const int*)d_in[1];
    const float* W1    = (const float*)d_in[2];
    const float* b1    = (const float*)d_in[3];
    const float* W2    = (const float*)d_in[4];
    const float* b2    = (const float*)d_in[5];
    const float* W3    = (const float*)d_in[6];
    const float* b3    = (const float*)d_in[7];
    const float* W4    = (const float*)d_in[8];
    const float* b4    = (const float*)d_in[9];
    float* out = (float*)d_out;

    int B = in_sizes[0] / DD;
    int grid = B / TM;

    cudaFuncSetAttribute(gym_mma, cudaFuncAttributeMaxDynamicSharedMemorySize,
                         SMEM_BYTES);
    gym_mma<<<grid, NT, SMEM_BYTES>>>(state, idx, W1, b1, W2, b2, W3, b3, W4,
                                      b4, out);
}